// round 15
// baseline (speedup 1.0000x reference)
#include <cuda_runtime.h>
#include <cuda_bf16.h>
#include <cuda_fp16.h>
#include <cstdint>

// ===========================================================================
// MHA  B=2 S=2048 DM=1024 H=16 DK=64 — Round 14:
//   proj/out: R12 2-stage cp.async pipeline (best known), 128x128 fp16 tiles
//   flash   : double-buffered K/V — 1 barrier per chunk, V prefetched a full
//             iteration ahead (register softmax => no barrier before PV)
// ===========================================================================

#define B_    2
#define S_    2048
#define H_    16
#define DK    64
#define DM    1024
#define MROWS (B_ * S_)   // 4096
#define BH    (B_ * H_)   // 32

typedef unsigned short u16;

// ---------------- device scratch ----------------
__device__ u16 g_Q16[MROWS * DM], g_K16in[MROWS * DM], g_V16[MROWS * DM];
__device__ u16 g_Wq16[DM * DM], g_Wk16[DM * DM], g_Wv16[DM * DM], g_Wo16[DM * DM];
__device__ u16 g_q16[BH * S_ * DK];            // fp16, pre-scaled by 0.125
__device__ u16 g_k16[BH * S_ * DK];
__device__ u16 g_vT16[BH * DK * S_];           // transposed V
__device__ u16 g_ctx16[MROWS * DM];

// ---------------- helpers ----------------
__device__ __forceinline__ uint32_t smem_u32(const void* p) {
    uint32_t a;
    asm("{ .reg .u64 t; cvta.to.shared.u64 t, %1; cvt.u32.u64 %0, t; }" : "=r"(a) : "l"(p));
    return a;
}
#define SWZ(b) ((b) ^ (((b) >> 3) & 0x70))

__device__ __forceinline__ void ldsm4(uint32_t r[4], uint32_t addr) {
    asm volatile("ldmatrix.sync.aligned.m8n8.x4.shared.b16 {%0,%1,%2,%3}, [%4];"
        : "=r"(r[0]), "=r"(r[1]), "=r"(r[2]), "=r"(r[3]) : "r"(addr));
}
__device__ __forceinline__ void cpa16(uint32_t dst, const void* src) {
    asm volatile("cp.async.cg.shared.global [%0], [%1], 16;" :: "r"(dst), "l"(src) : "memory");
}
#define CP_COMMIT() asm volatile("cp.async.commit_group;" ::: "memory")
#define CP_WAIT0()  asm volatile("cp.async.wait_group 0;" ::: "memory")
#define CP_WAIT1()  asm volatile("cp.async.wait_group 1;" ::: "memory")
#define CP_WAIT2()  asm volatile("cp.async.wait_group 2;" ::: "memory")

__device__ __forceinline__ void hmma_f16(float c[4], const uint32_t a[4], const uint32_t b[2]) {
    asm volatile("mma.sync.aligned.m16n8k16.row.col.f32.f16.f16.f32 "
        "{%0,%1,%2,%3}, {%4,%5,%6,%7}, {%8,%9}, {%0,%1,%2,%3};"
        : "+f"(c[0]), "+f"(c[1]), "+f"(c[2]), "+f"(c[3])
        : "r"(a[0]), "r"(a[1]), "r"(a[2]), "r"(a[3]), "r"(b[0]), "r"(b[1]));
}
__device__ __forceinline__ uint32_t pkh2(float a, float b) {
    __half2 h2 = __floats2half2_rn(a, b);
    return *(uint32_t*)&h2;
}

// ---------------- proj/out pipelined smem: 2 stages x 32 KB ----------------
#define STG_A  0
#define STG_B  16384
#define STG_SZ 32768
#define GE_SZ  (2 * STG_SZ)   // 64 KB dynamic

// ---------------------------------------------------------------------------
// GEMM mainloop: block 128(M) x 128(N), warp tile 32x64, 2-stage cp.async.
// ---------------------------------------------------------------------------
__device__ __forceinline__ void mma_loop(
    const u16* __restrict__ Ap, int lda,
    const u16* __restrict__ Bp, int ldb,
    int K, char* sm, float acc[2][8][4])
{
    const int tid  = threadIdx.x;
    const int lane = tid & 31;
    const int wid  = tid >> 5;
    const int wm   = wid >> 1;
    const int wn   = wid & 1;
    const uint32_t smb = smem_u32(sm);

    const int rA  = wm * 32 + (lane & 15);
    const int cA  = (lane >> 4) << 4;
    const int rB0 = wn * 64 + (lane & 7) + ((lane & 16) >> 1);
    const int cB  = (lane & 8) << 1;

    auto issue = [&](int ch, uint32_t st) {
        const int k0 = ch << 6;
#pragma unroll
        for (int i = 0; i < 4; i++) {
            int e = (tid + (i << 8)) << 3;
            int row = e >> 6, col = e & 63;
            uint32_t sw = SWZ((uint32_t)(row * 128 + col * 2));
            cpa16(st + STG_A + sw, Ap + (size_t)row * lda + k0 + col);
            cpa16(st + STG_B + sw, Bp + (size_t)row * ldb + k0 + col);
        }
    };

    const int nch = K >> 6;
    issue(0, smb); CP_COMMIT();
    for (int ch = 0; ch < nch; ch++) {
        CP_WAIT0();
        __syncthreads();
        if (ch + 1 < nch) { issue(ch + 1, smb + ((ch + 1) & 1) * STG_SZ); CP_COMMIT(); }
        const uint32_t st = smb + (ch & 1) * STG_SZ;
#pragma unroll
        for (int ks = 0; ks < 4; ks++) {
            uint32_t a[2][4];
            ldsm4(a[0], st + STG_A + SWZ((uint32_t)((rA)      * 128 + cA + ks * 32)));
            ldsm4(a[1], st + STG_A + SWZ((uint32_t)((rA + 16) * 128 + cA + ks * 32)));
            uint32_t b[4][4];
#pragma unroll
            for (int nb = 0; nb < 4; nb++)
                ldsm4(b[nb], st + STG_B + SWZ((uint32_t)((rB0 + 16 * nb) * 128 + cB + ks * 32)));
#pragma unroll
            for (int i = 0; i < 2; i++)
#pragma unroll
                for (int j = 0; j < 8; j++) {
                    uint32_t bb[2] = { b[j >> 1][(j & 1) * 2], b[j >> 1][(j & 1) * 2 + 1] };
                    hmma_f16(acc[i][j], a[i], bb);
                }
        }
    }
}

// ---------------------------------------------------------------------------
// cvt (merged): all 7 fp32 tensors -> single fp16. One launch.
// ---------------------------------------------------------------------------
#define NX4 (MROWS * DM / 4)
#define NW4 (DM * DM / 4)
__global__ void cvt_kernel(const float* __restrict__ Q, const float* __restrict__ K,
                           const float* __restrict__ V, const float* __restrict__ Wq,
                           const float* __restrict__ Wk, const float* __restrict__ Wv,
                           const float* __restrict__ Wo)
{
    int i = blockIdx.x * blockDim.x + threadIdx.x;
    const float* src; u16* dst; int off;
    if (i < NX4)          { src = Q;  dst = g_Q16;   off = i; }
    else if (i < 2 * NX4) { src = K;  dst = g_K16in; off = i - NX4; }
    else if (i < 3 * NX4) { src = V;  dst = g_V16;   off = i - 2 * NX4; }
    else {
        int w = i - 3 * NX4;
        int t = w / NW4; off = w - t * NW4;
        if (t == 0)      { src = Wq; dst = g_Wq16; }
        else if (t == 1) { src = Wk; dst = g_Wk16; }
        else if (t == 2) { src = Wv; dst = g_Wv16; }
        else             { src = Wo; dst = g_Wo16; }
    }
    float4 v = ((const float4*)src)[off];
    ((uint2*)dst)[off] = make_uint2(pkh2(v.x, v.y), pkh2(v.z, v.w));
}

// ---------------------------------------------------------------------------
// proj: z=0 -> q (fp16, x0.125), z=1 -> k, z=2 -> vT. grid (8, 32, 3)
// ---------------------------------------------------------------------------
__global__ __launch_bounds__(256) void proj_kernel(
    const float* __restrict__ bq, const float* __restrict__ bk,
    const float* __restrict__ bv)
{
    extern __shared__ char sm[];
    const int z  = blockIdx.z;
    const int n0 = blockIdx.x * 128;
    const int m0 = blockIdx.y * 128;

    const u16 *Ap, *Bp;
    const float* bias;
    if (z == 0)      { Ap = g_Q16;   Bp = g_Wq16; bias = bq; }
    else if (z == 1) { Ap = g_K16in; Bp = g_Wk16; bias = bk; }
    else             { Ap = g_V16;   Bp = g_Wv16; bias = bv; }

    float acc[2][8][4];
#pragma unroll
    for (int i = 0; i < 2; i++)
#pragma unroll
        for (int j = 0; j < 8; j++)
#pragma unroll
            for (int q = 0; q < 4; q++) acc[i][j][q] = 0.f;

    mma_loop(Ap + (size_t)m0 * DM, DM, Bp + (size_t)n0 * DM, DM, DM, sm, acc);

    const int lane = threadIdx.x & 31, wid = threadIdx.x >> 5;
    const int wm = wid >> 1, wn = wid & 1;
#pragma unroll
    for (int i = 0; i < 2; i++)
#pragma unroll
    for (int half = 0; half < 2; half++) {
        const int r = m0 + wm * 32 + i * 16 + (lane >> 2) + half * 8;
        const int b = r >> 11, s = r & (S_ - 1);
#pragma unroll
        for (int j = 0; j < 8; j++) {
            const int n = n0 + wn * 64 + j * 8 + 2 * (lane & 3);
            float v0 = acc[i][j][half * 2]     + bias[n];
            float v1 = acc[i][j][half * 2 + 1] + bias[n + 1];
            const int hh = n >> 6, dk = n & 63;
            const size_t bh = (size_t)(b * H_ + hh);
            if (z == 0) {
                *(uint32_t*)&g_q16[(bh * S_ + s) * DK + dk] = pkh2(v0 * 0.125f, v1 * 0.125f);
            } else if (z == 1) {
                *(uint32_t*)&g_k16[(bh * S_ + s) * DK + dk] = pkh2(v0, v1);
            } else {
                __half h0 = __float2half_rn(v0), h1 = __float2half_rn(v1);
                g_vT16[(bh * DK + dk)     * S_ + s] = *(u16*)&h0;
                g_vT16[(bh * DK + dk + 1) * S_ + s] = *(u16*)&h1;
            }
        }
    }
}

// ---------------- flash smem layout (dynamic, 48 KB) ----------------
#define FQ    0          // 16 KB fp16 q tile (128 x 64)
#define FK0   16384      // 8 KB  K buf 0
#define FK1   24576      // 8 KB  K buf 1
#define FV0   32768      // 8 KB  V buf 0
#define FV1   40960      // 8 KB  V buf 1
#define FL_SZ 49152

// ---------------------------------------------------------------------------
// flash: fused scores+softmax+pv, fp16 MMA, register-P, DOUBLE-BUFFERED K/V.
// One barrier per chunk; V prefetched a full iteration ahead.
// grid (16, BH), 256 threads.
// ---------------------------------------------------------------------------
__global__ __launch_bounds__(256, 2) void flash_kernel()
{
    extern __shared__ char sm[];
    const uint32_t smb = smem_u32(sm);

    const int bh = blockIdx.y;
    const int m0 = blockIdx.x * 128;
    const size_t qoff = (size_t)bh * S_ * DK;
    const size_t voff = (size_t)bh * DK * S_;

    const int tid  = threadIdx.x;
    const int lane = tid & 31;
    const int wid  = tid >> 5;
    const int g    = lane >> 2;
    const int tq   = lane & 3;

    const int rA  = wid * 16 + (lane & 15);
    const int cA  = (lane >> 4) << 4;
    const int rB0 = (lane & 7) + ((lane & 16) >> 1);
    const int cB  = (lane & 8) << 1;

    auto issueK = [&](int n0, int buf) {
        const uint32_t base = smb + (buf ? FK1 : FK0);
#pragma unroll
        for (int i = 0; i < 2; i++) {
            int e = (tid + (i << 8)) << 3;
            int row = e >> 6, col = e & 63;
            uint32_t sw = SWZ((uint32_t)(row * 128 + col * 2));
            cpa16(base + sw, g_k16 + qoff + (size_t)(n0 + row) * DK + col);
        }
    };
    auto issueV = [&](int n0, int buf) {
        const uint32_t base = smb + (buf ? FV1 : FV0);
#pragma unroll
        for (int i = 0; i < 2; i++) {
            int e = (tid + (i << 8)) << 3;
            int row = e >> 6, col = e & 63;     // row = dk, col = key
            uint32_t sw = SWZ((uint32_t)(row * 128 + col * 2));
            cpa16(base + sw, g_vT16 + voff + (size_t)row * S_ + n0 + col);
        }
    };

    // ---- prologue: {Q, K0} commit, {V0} commit ----
#pragma unroll
    for (int i = 0; i < 4; i++) {
        int e = (tid + (i << 8)) << 3;
        int row = e >> 6, col = e & 63;
        uint32_t sw = SWZ((uint32_t)(row * 128 + col * 2));
        cpa16(smb + FQ + sw, g_q16 + qoff + (size_t)(m0 + row) * DK + col);
    }
    issueK(0, 0);
    CP_COMMIT();
    issueV(0, 0);
    CP_COMMIT();

    float acc_o[8][4];
#pragma unroll
    for (int j = 0; j < 8; j++)
#pragma unroll
        for (int q = 0; q < 4; q++) acc_o[j][q] = 0.f;
    float m0r = -1e30f, m1r = -1e30f, s0r = 0.f, s1r = 0.f;

    const int NCH = S_ / 64;
    for (int ch = 0; ch < NCH; ch++) {
        const int n0 = ch << 6;
        const uint32_t kbuf = smb + ((ch & 1) ? FK1 : FK0);
        const uint32_t vbuf = smb + ((ch & 1) ? FV1 : FV0);

        // pending here: {K(ch)}, {V(ch)} -> wait_group 1 => K(ch) resident
        CP_WAIT1();
        __syncthreads();   // all warps done with K(ch-1)/V(ch-1) buffers

        if (ch + 1 < NCH) {
            issueK(n0 + 64, (ch + 1) & 1); CP_COMMIT();
            issueV(n0 + 64, (ch + 1) & 1); CP_COMMIT();
        }

        // ---- S = q k^T, single-pass fp16 (q pre-scaled) ----
        float s[8][4];
#pragma unroll
        for (int j = 0; j < 8; j++)
#pragma unroll
            for (int q = 0; q < 4; q++) s[j][q] = 0.f;
#pragma unroll
        for (int ks = 0; ks < 4; ks++) {
            uint32_t a[4];
            ldsm4(a, smb + FQ + SWZ((uint32_t)(rA * 128 + cA + ks * 32)));
            uint32_t b[4][4];
#pragma unroll
            for (int nb = 0; nb < 4; nb++)
                ldsm4(b[nb], kbuf + SWZ((uint32_t)((rB0 + 16 * nb) * 128 + cB + ks * 32)));
#pragma unroll
            for (int j = 0; j < 8; j++) {
                uint32_t bb[2] = { b[j >> 1][(j & 1) * 2], b[j >> 1][(j & 1) * 2 + 1] };
                hmma_f16(s[j], a, bb);
            }
        }

        // ---- online softmax, fully in registers (rows g and g+8) ----
        float mx0 = -1e30f, mx1 = -1e30f;
#pragma unroll
        for (int j = 0; j < 8; j++) {
            mx0 = fmaxf(mx0, fmaxf(s[j][0], s[j][1]));
            mx1 = fmaxf(mx1, fmaxf(s[j][2], s[j][3]));
        }
        mx0 = fmaxf(mx0, __shfl_xor_sync(~0u, mx0, 1));
        mx0 = fmaxf(mx0, __shfl_xor_sync(~0u, mx0, 2));
        mx1 = fmaxf(mx1, __shfl_xor_sync(~0u, mx1, 1));
        mx1 = fmaxf(mx1, __shfl_xor_sync(~0u, mx1, 2));

        const float mn0 = fmaxf(m0r, mx0), mn1 = fmaxf(m1r, mx1);
        const float al0 = __expf(m0r - mn0), al1 = __expf(m1r - mn1);
        m0r = mn0; m1r = mn1;

        float ps0 = 0.f, ps1 = 0.f;
#pragma unroll
        for (int j = 0; j < 8; j++) {
            s[j][0] = __expf(s[j][0] - mn0);
            s[j][1] = __expf(s[j][1] - mn0);
            s[j][2] = __expf(s[j][2] - mn1);
            s[j][3] = __expf(s[j][3] - mn1);
            ps0 += s[j][0] + s[j][1];
            ps1 += s[j][2] + s[j][3];
            acc_o[j][0] *= al0; acc_o[j][1] *= al0;
            acc_o[j][2] *= al1; acc_o[j][3] *= al1;
        }
        ps0 += __shfl_xor_sync(~0u, ps0, 1);
        ps0 += __shfl_xor_sync(~0u, ps0, 2);
        ps1 += __shfl_xor_sync(~0u, ps1, 1);
        ps1 += __shfl_xor_sync(~0u, ps1, 2);
        s0r = s0r * al0 + ps0;
        s1r = s1r * al1 + ps1;

        // pending: {V(ch)}, and if issued {K(ch+1)},{V(ch+1)}.
        // wait_group 2 when new groups exist (V(ch) done), else drain all.
        if (ch + 1 < NCH) CP_WAIT2(); else CP_WAIT0();
        // no barrier needed: softmax is register-only, V(ch) buffer untouched
        // by any smem write since the iteration-top barrier.

        // ---- O += P @ V, single-pass fp16, P packed from registers ----
#pragma unroll
        for (int ks = 0; ks < 4; ks++) {
            uint32_t a[4];
            a[0] = pkh2(s[2 * ks][0],     s[2 * ks][1]);
            a[1] = pkh2(s[2 * ks][2],     s[2 * ks][3]);
            a[2] = pkh2(s[2 * ks + 1][0], s[2 * ks + 1][1]);
            a[3] = pkh2(s[2 * ks + 1][2], s[2 * ks + 1][3]);
            uint32_t v[4][4];
#pragma unroll
            for (int nb = 0; nb < 4; nb++)
                ldsm4(v[nb], vbuf + SWZ((uint32_t)((rB0 + 16 * nb) * 128 + cB + ks * 32)));
#pragma unroll
            for (int j = 0; j < 8; j++) {
                uint32_t bb[2] = { v[j >> 1][(j & 1) * 2], v[j >> 1][(j & 1) * 2 + 1] };
                hmma_f16(acc_o[j], a, bb);
            }
        }
    }

    // ---- epilogue: normalize, write ctx (single fp16) ----
    const int b = bh >> 4, h = bh & 15;
    const float inv0 = 1.0f / s0r, inv1 = 1.0f / s1r;
    const int r0 = m0 + wid * 16 + g;
    const size_t ro0 = ((size_t)(b * S_ + r0)) * DM + h * DK;
    const size_t ro1 = ro0 + (size_t)8 * DM;
#pragma unroll
    for (int j = 0; j < 8; j++) {
        const int d = 8 * j + 2 * tq;
        *(uint32_t*)&g_ctx16[ro0 + d] = pkh2(acc_o[j][0] * inv0, acc_o[j][1] * inv0);
        *(uint32_t*)&g_ctx16[ro1 + d] = pkh2(acc_o[j][2] * inv1, acc_o[j][3] * inv1);
    }
}

// ---------------------------------------------------------------------------
// out: out = ctx @ Wo^T + bo.  grid (8, 32)
// ---------------------------------------------------------------------------
__global__ __launch_bounds__(256) void out_kernel(float* __restrict__ out,
                                                  const float* __restrict__ bo)
{
    extern __shared__ char sm[];
    const int n0 = blockIdx.x * 128;
    const int m0 = blockIdx.y * 128;

    float acc[2][8][4];
#pragma unroll
    for (int i = 0; i < 2; i++)
#pragma unroll
        for (int j = 0; j < 8; j++)
#pragma unroll
            for (int q = 0; q < 4; q++) acc[i][j][q] = 0.f;

    mma_loop(g_ctx16 + (size_t)m0 * DM, DM, g_Wo16 + (size_t)n0 * DM, DM, DM, sm, acc);

    const int lane = threadIdx.x & 31, wid = threadIdx.x >> 5;
    const int wm = wid >> 1, wn = wid & 1;
#pragma unroll
    for (int i = 0; i < 2; i++)
#pragma unroll
    for (int half = 0; half < 2; half++) {
        const int r = m0 + wm * 32 + i * 16 + (lane >> 2) + half * 8;
#pragma unroll
        for (int j = 0; j < 8; j++) {
            const int c = n0 + wn * 64 + j * 8 + 2 * (lane & 3);
            float2 o = { acc[i][j][half * 2] + bo[c],
                         acc[i][j][half * 2 + 1] + bo[c + 1] };
            *(float2*)(out + (size_t)r * DM + c) = o;
        }
    }
}

// ---------------------------------------------------------------------------
// launcher — no __device__ symbol referenced from host code.
// ---------------------------------------------------------------------------
extern "C" void kernel_launch(void* const* d_in, const int* in_sizes, int n_in,
                              void* d_out, int out_size)
{
    (void)in_sizes; (void)n_in; (void)out_size;
    const float* Q  = (const float*)d_in[0];
    const float* K  = (const float*)d_in[1];
    const float* V  = (const float*)d_in[2];
    const float* bq = (const float*)d_in[4];
    const float* bk = (const float*)d_in[6];
    const float* bv = (const float*)d_in[8];
    const float* bo = (const float*)d_in[10];
    float* out = (float*)d_out;

    cudaFuncSetAttribute(proj_kernel,  cudaFuncAttributeMaxDynamicSharedMemorySize, GE_SZ);
    cudaFuncSetAttribute(out_kernel,   cudaFuncAttributeMaxDynamicSharedMemorySize, GE_SZ);
    cudaFuncSetAttribute(flash_kernel, cudaFuncAttributeMaxDynamicSharedMemorySize, FL_SZ);

    const int total4 = 3 * NX4 + 4 * NW4;
    cvt_kernel<<<total4 / 256, 256>>>(Q, K, V,
                                      (const float*)d_in[3], (const float*)d_in[5],
                                      (const float*)d_in[7], (const float*)d_in[9]);

    proj_kernel <<<dim3(DM / 128, MROWS / 128, 3), 256, GE_SZ>>>(bq, bk, bv);
    flash_kernel<<<dim3(S_ / 128, BH), 256, FL_SZ>>>();
    out_kernel  <<<dim3(DM / 128, MROWS / 128),   256, GE_SZ>>>(out, bo);
}

// round 16
// speedup vs baseline: 1.0147x; 1.0147x over previous
#include <cuda_runtime.h>
#include <cuda_bf16.h>
#include <cuda_fp16.h>
#include <cstdint>

// ===========================================================================
// MHA  B=2 S=2048 DM=1024 H=16 DK=64 — Round 15:
//   base = R12 (best known: 2-stage cp.async 128x128 fp16 GEMMs, fused flash)
//   + proj vT epilogue: smem-transposed coalesced store (kills 16x write
//     amplification of the strided 2-byte vT writes)
// ===========================================================================

#define B_    2
#define S_    2048
#define H_    16
#define DK    64
#define DM    1024
#define MROWS (B_ * S_)   // 4096
#define BH    (B_ * H_)   // 32

typedef unsigned short u16;

// ---------------- device scratch ----------------
__device__ u16 g_Q16[MROWS * DM], g_K16in[MROWS * DM], g_V16[MROWS * DM];
__device__ u16 g_Wq16[DM * DM], g_Wk16[DM * DM], g_Wv16[DM * DM], g_Wo16[DM * DM];
__device__ u16 g_q16[BH * S_ * DK];            // fp16, pre-scaled by 0.125
__device__ u16 g_k16[BH * S_ * DK];
__device__ u16 g_vT16[BH * DK * S_];           // transposed V
__device__ u16 g_ctx16[MROWS * DM];

// ---------------- helpers ----------------
__device__ __forceinline__ uint32_t smem_u32(const void* p) {
    uint32_t a;
    asm("{ .reg .u64 t; cvta.to.shared.u64 t, %1; cvt.u32.u64 %0, t; }" : "=r"(a) : "l"(p));
    return a;
}
#define SWZ(b) ((b) ^ (((b) >> 3) & 0x70))

__device__ __forceinline__ void ldsm4(uint32_t r[4], uint32_t addr) {
    asm volatile("ldmatrix.sync.aligned.m8n8.x4.shared.b16 {%0,%1,%2,%3}, [%4];"
        : "=r"(r[0]), "=r"(r[1]), "=r"(r[2]), "=r"(r[3]) : "r"(addr));
}
__device__ __forceinline__ void cpa16(uint32_t dst, const void* src) {
    asm volatile("cp.async.cg.shared.global [%0], [%1], 16;" :: "r"(dst), "l"(src) : "memory");
}
#define CP_COMMIT() asm volatile("cp.async.commit_group;" ::: "memory")
#define CP_WAIT0()  asm volatile("cp.async.wait_group 0;" ::: "memory")

__device__ __forceinline__ void hmma_f16(float c[4], const uint32_t a[4], const uint32_t b[2]) {
    asm volatile("mma.sync.aligned.m16n8k16.row.col.f32.f16.f16.f32 "
        "{%0,%1,%2,%3}, {%4,%5,%6,%7}, {%8,%9}, {%0,%1,%2,%3};"
        : "+f"(c[0]), "+f"(c[1]), "+f"(c[2]), "+f"(c[3])
        : "r"(a[0]), "r"(a[1]), "r"(a[2]), "r"(a[3]), "r"(b[0]), "r"(b[1]));
}
__device__ __forceinline__ uint32_t pkh2(float a, float b) {
    __half2 h2 = __floats2half2_rn(a, b);
    return *(uint32_t*)&h2;
}

// ---------------- proj/out pipelined smem: 2 stages x 32 KB ----------------
#define STG_A  0
#define STG_B  16384
#define STG_SZ 32768
#define GE_SZ  (2 * STG_SZ)   // 64 KB dynamic (also reused as vT staging)

// ---------------------------------------------------------------------------
// GEMM mainloop: block 128(M) x 128(N), warp tile 32x64, 2-stage cp.async.
// ---------------------------------------------------------------------------
__device__ __forceinline__ void mma_loop(
    const u16* __restrict__ Ap, int lda,
    const u16* __restrict__ Bp, int ldb,
    int K, char* sm, float acc[2][8][4])
{
    const int tid  = threadIdx.x;
    const int lane = tid & 31;
    const int wid  = tid >> 5;
    const int wm   = wid >> 1;
    const int wn   = wid & 1;
    const uint32_t smb = smem_u32(sm);

    const int rA  = wm * 32 + (lane & 15);
    const int cA  = (lane >> 4) << 4;
    const int rB0 = wn * 64 + (lane & 7) + ((lane & 16) >> 1);
    const int cB  = (lane & 8) << 1;

    auto issue = [&](int ch, uint32_t st) {
        const int k0 = ch << 6;
#pragma unroll
        for (int i = 0; i < 4; i++) {
            int e = (tid + (i << 8)) << 3;
            int row = e >> 6, col = e & 63;
            uint32_t sw = SWZ((uint32_t)(row * 128 + col * 2));
            cpa16(st + STG_A + sw, Ap + (size_t)row * lda + k0 + col);
            cpa16(st + STG_B + sw, Bp + (size_t)row * ldb + k0 + col);
        }
    };

    const int nch = K >> 6;
    issue(0, smb); CP_COMMIT();
    for (int ch = 0; ch < nch; ch++) {
        CP_WAIT0();
        __syncthreads();
        if (ch + 1 < nch) { issue(ch + 1, smb + ((ch + 1) & 1) * STG_SZ); CP_COMMIT(); }
        const uint32_t st = smb + (ch & 1) * STG_SZ;
#pragma unroll
        for (int ks = 0; ks < 4; ks++) {
            uint32_t a[2][4];
            ldsm4(a[0], st + STG_A + SWZ((uint32_t)((rA)      * 128 + cA + ks * 32)));
            ldsm4(a[1], st + STG_A + SWZ((uint32_t)((rA + 16) * 128 + cA + ks * 32)));
            uint32_t b[4][4];
#pragma unroll
            for (int nb = 0; nb < 4; nb++)
                ldsm4(b[nb], st + STG_B + SWZ((uint32_t)((rB0 + 16 * nb) * 128 + cB + ks * 32)));
#pragma unroll
            for (int i = 0; i < 2; i++)
#pragma unroll
                for (int j = 0; j < 8; j++) {
                    uint32_t bb[2] = { b[j >> 1][(j & 1) * 2], b[j >> 1][(j & 1) * 2 + 1] };
                    hmma_f16(acc[i][j], a[i], bb);
                }
        }
    }
}

// ---------------------------------------------------------------------------
// cvt (merged): all 7 fp32 tensors -> single fp16. One launch.
// ---------------------------------------------------------------------------
#define NX4 (MROWS * DM / 4)
#define NW4 (DM * DM / 4)
__global__ void cvt_kernel(const float* __restrict__ Q, const float* __restrict__ K,
                           const float* __restrict__ V, const float* __restrict__ Wq,
                           const float* __restrict__ Wk, const float* __restrict__ Wv,
                           const float* __restrict__ Wo)
{
    int i = blockIdx.x * blockDim.x + threadIdx.x;
    const float* src; u16* dst; int off;
    if (i < NX4)          { src = Q;  dst = g_Q16;   off = i; }
    else if (i < 2 * NX4) { src = K;  dst = g_K16in; off = i - NX4; }
    else if (i < 3 * NX4) { src = V;  dst = g_V16;   off = i - 2 * NX4; }
    else {
        int w = i - 3 * NX4;
        int t = w / NW4; off = w - t * NW4;
        if (t == 0)      { src = Wq; dst = g_Wq16; }
        else if (t == 1) { src = Wk; dst = g_Wk16; }
        else if (t == 2) { src = Wv; dst = g_Wv16; }
        else             { src = Wo; dst = g_Wo16; }
    }
    float4 v = ((const float4*)src)[off];
    ((uint2*)dst)[off] = make_uint2(pkh2(v.x, v.y), pkh2(v.z, v.w));
}

// ---------------------------------------------------------------------------
// proj: z=0 -> q (fp16, x0.125), z=1 -> k, z=2 -> vT (smem-transposed store).
// grid (8, 32, 3)
// ---------------------------------------------------------------------------
#define VT_STRIDE 136   // u16 row stride for staging (pad vs 128 to dodge conflicts)

__global__ __launch_bounds__(256) void proj_kernel(
    const float* __restrict__ bq, const float* __restrict__ bk,
    const float* __restrict__ bv)
{
    extern __shared__ char sm[];
    const int z  = blockIdx.z;
    const int n0 = blockIdx.x * 128;
    const int m0 = blockIdx.y * 128;

    const u16 *Ap, *Bp;
    const float* bias;
    if (z == 0)      { Ap = g_Q16;   Bp = g_Wq16; bias = bq; }
    else if (z == 1) { Ap = g_K16in; Bp = g_Wk16; bias = bk; }
    else             { Ap = g_V16;   Bp = g_Wv16; bias = bv; }

    float acc[2][8][4];
#pragma unroll
    for (int i = 0; i < 2; i++)
#pragma unroll
        for (int j = 0; j < 8; j++)
#pragma unroll
            for (int q = 0; q < 4; q++) acc[i][j][q] = 0.f;

    mma_loop(Ap + (size_t)m0 * DM, DM, Bp + (size_t)n0 * DM, DM, DM, sm, acc);

    const int tid  = threadIdx.x;
    const int lane = tid & 31, wid = tid >> 5;
    const int wm = wid >> 1, wn = wid & 1;

    if (z != 2) {
#pragma unroll
        for (int i = 0; i < 2; i++)
#pragma unroll
        for (int half = 0; half < 2; half++) {
            const int r = m0 + wm * 32 + i * 16 + (lane >> 2) + half * 8;
            const int b = r >> 11, s = r & (S_ - 1);
#pragma unroll
            for (int j = 0; j < 8; j++) {
                const int n = n0 + wn * 64 + j * 8 + 2 * (lane & 3);
                float v0 = acc[i][j][half * 2]     + bias[n];
                float v1 = acc[i][j][half * 2 + 1] + bias[n + 1];
                const int hh = n >> 6, dk = n & 63;
                const size_t bh = (size_t)(b * H_ + hh);
                if (z == 0) {
                    *(uint32_t*)&g_q16[(bh * S_ + s) * DK + dk] = pkh2(v0 * 0.125f, v1 * 0.125f);
                } else {
                    *(uint32_t*)&g_k16[(bh * S_ + s) * DK + dk] = pkh2(v0, v1);
                }
            }
        }
    } else {
        // ---- vT: stage transposed tile [n_local][s_local] in smem, then
        //      cooperatively store coalesced 128B runs per dk-row ----
        u16* stg = (u16*)sm;
        __syncthreads();   // mainloop smem reads done before overwrite
#pragma unroll
        for (int i = 0; i < 2; i++)
#pragma unroll
        for (int half = 0; half < 2; half++) {
            const int s_local = wm * 32 + i * 16 + (lane >> 2) + half * 8;
#pragma unroll
            for (int j = 0; j < 8; j++) {
                const int nl = wn * 64 + j * 8 + 2 * (lane & 3);
                const int n  = n0 + nl;
                __half h0 = __float2half_rn(acc[i][j][half * 2]     + bias[n]);
                __half h1 = __float2half_rn(acc[i][j][half * 2 + 1] + bias[n + 1]);
                stg[(nl)     * VT_STRIDE + s_local] = *(u16*)&h0;
                stg[(nl + 1) * VT_STRIDE + s_local] = *(u16*)&h1;
            }
        }
        __syncthreads();

        const int nl = tid >> 1;               // 0..127
        const int sh = (tid & 1) * 64;         // s-half
        const int n  = n0 + nl;
        const int hh = n >> 6, dk = n & 63;
        const int b  = m0 >> 11;
        const int sb = (m0 & (S_ - 1)) + sh;
        const size_t bh = (size_t)(b * H_ + hh);
        const uint4* src = (const uint4*)(stg + nl * VT_STRIDE + sh);
        uint4* dst = (uint4*)(g_vT16 + (bh * DK + dk) * S_ + sb);
#pragma unroll
        for (int u = 0; u < 8; u++) dst[u] = src[u];
    }
}

// ---------------- flash smem layout (dynamic, 32 KB) ----------------
#define FQ  0          // 16 KB fp16 q tile (128 x 64)
#define FK  16384      // 8 KB  fp16 K chunk (64 x 64)
#define FV  24576      // 8 KB  fp16 vT chunk (64 dk x 64 keys)
#define FL_SZ 32768

// ---------------------------------------------------------------------------
// flash: fused scores+softmax+pv, all fp16 MMA, register-P.
// warp = 16 rows x 64 keys. grid (16, BH), 256 threads.
// ---------------------------------------------------------------------------
__global__ __launch_bounds__(256, 2) void flash_kernel()
{
    extern __shared__ char sm[];
    const uint32_t smb = smem_u32(sm);

    const int bh = blockIdx.y;
    const int m0 = blockIdx.x * 128;
    const size_t qoff = (size_t)bh * S_ * DK;
    const size_t voff = (size_t)bh * DK * S_;

    const int tid  = threadIdx.x;
    const int lane = tid & 31;
    const int wid  = tid >> 5;
    const int g    = lane >> 2;
    const int tq   = lane & 3;

    const int rA  = wid * 16 + (lane & 15);
    const int cA  = (lane >> 4) << 4;
    const int rB0 = (lane & 7) + ((lane & 16) >> 1);
    const int cB  = (lane & 8) << 1;

    auto issueK = [&](int n0) {
#pragma unroll
        for (int i = 0; i < 2; i++) {
            int e = (tid + (i << 8)) << 3;
            int row = e >> 6, col = e & 63;
            uint32_t sw = SWZ((uint32_t)(row * 128 + col * 2));
            cpa16(smb + FK + sw, g_k16 + qoff + (size_t)(n0 + row) * DK + col);
        }
    };
    auto issueV = [&](int n0) {
#pragma unroll
        for (int i = 0; i < 2; i++) {
            int e = (tid + (i << 8)) << 3;
            int row = e >> 6, col = e & 63;     // row = dk, col = key
            uint32_t sw = SWZ((uint32_t)(row * 128 + col * 2));
            cpa16(smb + FV + sw, g_vT16 + voff + (size_t)row * S_ + n0 + col);
        }
    };

    // ---- issue Q (persistent) + K chunk 0 ----
#pragma unroll
    for (int i = 0; i < 4; i++) {
        int e = (tid + (i << 8)) << 3;
        int row = e >> 6, col = e & 63;
        uint32_t sw = SWZ((uint32_t)(row * 128 + col * 2));
        cpa16(smb + FQ + sw, g_q16 + qoff + (size_t)(m0 + row) * DK + col);
    }
    issueK(0);
    CP_COMMIT();

    float acc_o[8][4];
#pragma unroll
    for (int j = 0; j < 8; j++)
#pragma unroll
        for (int q = 0; q < 4; q++) acc_o[j][q] = 0.f;
    float m0r = -1e30f, m1r = -1e30f, s0r = 0.f, s1r = 0.f;

    for (int ch = 0; ch < S_ / 64; ch++) {
        const int n0 = ch << 6;

        CP_WAIT0();
        __syncthreads();                 // K(ch)+Q visible; all warps done with V(ch-1)
        issueV(n0); CP_COMMIT();         // V(ch) flies during S + softmax

        // ---- S = q k^T, single-pass fp16 (q pre-scaled) ----
        float s[8][4];
#pragma unroll
        for (int j = 0; j < 8; j++)
#pragma unroll
            for (int q = 0; q < 4; q++) s[j][q] = 0.f;
#pragma unroll
        for (int ks = 0; ks < 4; ks++) {
            uint32_t a[4];
            ldsm4(a, smb + FQ + SWZ((uint32_t)(rA * 128 + cA + ks * 32)));
            uint32_t b[4][4];
#pragma unroll
            for (int nb = 0; nb < 4; nb++)
                ldsm4(b[nb], smb + FK + SWZ((uint32_t)((rB0 + 16 * nb) * 128 + cB + ks * 32)));
#pragma unroll
            for (int j = 0; j < 8; j++) {
                uint32_t bb[2] = { b[j >> 1][(j & 1) * 2], b[j >> 1][(j & 1) * 2 + 1] };
                hmma_f16(s[j], a, bb);
            }
        }

        // ---- online softmax, fully in registers (rows g and g+8) ----
        float mx0 = -1e30f, mx1 = -1e30f;
#pragma unroll
        for (int j = 0; j < 8; j++) {
            mx0 = fmaxf(mx0, fmaxf(s[j][0], s[j][1]));
            mx1 = fmaxf(mx1, fmaxf(s[j][2], s[j][3]));
        }
        mx0 = fmaxf(mx0, __shfl_xor_sync(~0u, mx0, 1));
        mx0 = fmaxf(mx0, __shfl_xor_sync(~0u, mx0, 2));
        mx1 = fmaxf(mx1, __shfl_xor_sync(~0u, mx1, 1));
        mx1 = fmaxf(mx1, __shfl_xor_sync(~0u, mx1, 2));

        const float mn0 = fmaxf(m0r, mx0), mn1 = fmaxf(m1r, mx1);
        const float al0 = __expf(m0r - mn0), al1 = __expf(m1r - mn1);
        m0r = mn0; m1r = mn1;

        float ps0 = 0.f, ps1 = 0.f;
#pragma unroll
        for (int j = 0; j < 8; j++) {
            s[j][0] = __expf(s[j][0] - mn0);
            s[j][1] = __expf(s[j][1] - mn0);
            s[j][2] = __expf(s[j][2] - mn1);
            s[j][3] = __expf(s[j][3] - mn1);
            ps0 += s[j][0] + s[j][1];
            ps1 += s[j][2] + s[j][3];
            acc_o[j][0] *= al0; acc_o[j][1] *= al0;
            acc_o[j][2] *= al1; acc_o[j][3] *= al1;
        }
        ps0 += __shfl_xor_sync(~0u, ps0, 1);
        ps0 += __shfl_xor_sync(~0u, ps0, 2);
        ps1 += __shfl_xor_sync(~0u, ps1, 1);
        ps1 += __shfl_xor_sync(~0u, ps1, 2);
        s0r = s0r * al0 + ps0;
        s1r = s1r * al1 + ps1;

        CP_WAIT0();
        __syncthreads();                 // V(ch) visible; all warps done with K(ch)
        if (ch + 1 < S_ / 64) { issueK(n0 + 64); CP_COMMIT(); }  // K(ch+1) flies during PV

        // ---- O += P @ V, single-pass fp16, P packed from registers ----
#pragma unroll
        for (int ks = 0; ks < 4; ks++) {
            uint32_t a[4];
            a[0] = pkh2(s[2 * ks][0],     s[2 * ks][1]);
            a[1] = pkh2(s[2 * ks][2],     s[2 * ks][3]);
            a[2] = pkh2(s[2 * ks + 1][0], s[2 * ks + 1][1]);
            a[3] = pkh2(s[2 * ks + 1][2], s[2 * ks + 1][3]);
            uint32_t v[4][4];
#pragma unroll
            for (int nb = 0; nb < 4; nb++)
                ldsm4(v[nb], smb + FV + SWZ((uint32_t)((rB0 + 16 * nb) * 128 + cB + ks * 32)));
#pragma unroll
            for (int j = 0; j < 8; j++) {
                uint32_t bb[2] = { v[j >> 1][(j & 1) * 2], v[j >> 1][(j & 1) * 2 + 1] };
                hmma_f16(acc_o[j], a, bb);
            }
        }
    }

    // ---- epilogue: normalize, write ctx (single fp16) ----
    const int b = bh >> 4, h = bh & 15;
    const float inv0 = 1.0f / s0r, inv1 = 1.0f / s1r;
    const int r0 = m0 + wid * 16 + g;
    const size_t ro0 = ((size_t)(b * S_ + r0)) * DM + h * DK;
    const size_t ro1 = ro0 + (size_t)8 * DM;
#pragma unroll
    for (int j = 0; j < 8; j++) {
        const int d = 8 * j + 2 * tq;
        *(uint32_t*)&g_ctx16[ro0 + d] = pkh2(acc_o[j][0] * inv0, acc_o[j][1] * inv0);
        *(uint32_t*)&g_ctx16[ro1 + d] = pkh2(acc_o[j][2] * inv1, acc_o[j][3] * inv1);
    }
}

// ---------------------------------------------------------------------------
// out: out = ctx @ Wo^T + bo.  grid (8, 32)
// ---------------------------------------------------------------------------
__global__ __launch_bounds__(256) void out_kernel(float* __restrict__ out,
                                                  const float* __restrict__ bo)
{
    extern __shared__ char sm[];
    const int n0 = blockIdx.x * 128;
    const int m0 = blockIdx.y * 128;

    float acc[2][8][4];
#pragma unroll
    for (int i = 0; i < 2; i++)
#pragma unroll
        for (int j = 0; j < 8; j++)
#pragma unroll
            for (int q = 0; q < 4; q++) acc[i][j][q] = 0.f;

    mma_loop(g_ctx16 + (size_t)m0 * DM, DM, g_Wo16 + (size_t)n0 * DM, DM, DM, sm, acc);

    const int lane = threadIdx.x & 31, wid = threadIdx.x >> 5;
    const int wm = wid >> 1, wn = wid & 1;
#pragma unroll
    for (int i = 0; i < 2; i++)
#pragma unroll
    for (int half = 0; half < 2; half++) {
        const int r = m0 + wm * 32 + i * 16 + (lane >> 2) + half * 8;
#pragma unroll
        for (int j = 0; j < 8; j++) {
            const int c = n0 + wn * 64 + j * 8 + 2 * (lane & 3);
            float2 o = { acc[i][j][half * 2] + bo[c],
                         acc[i][j][half * 2 + 1] + bo[c + 1] };
            *(float2*)(out + (size_t)r * DM + c) = o;
        }
    }
}

// ---------------------------------------------------------------------------
// launcher — no __device__ symbol referenced from host code.
// ---------------------------------------------------------------------------
extern "C" void kernel_launch(void* const* d_in, const int* in_sizes, int n_in,
                              void* d_out, int out_size)
{
    (void)in_sizes; (void)n_in; (void)out_size;
    const float* Q  = (const float*)d_in[0];
    const float* K  = (const float*)d_in[1];
    const float* V  = (const float*)d_in[2];
    const float* bq = (const float*)d_in[4];
    const float* bk = (const float*)d_in[6];
    const float* bv = (const float*)d_in[8];
    const float* bo = (const float*)d_in[10];
    float* out = (float*)d_out;

    cudaFuncSetAttribute(proj_kernel,  cudaFuncAttributeMaxDynamicSharedMemorySize, GE_SZ);
    cudaFuncSetAttribute(out_kernel,   cudaFuncAttributeMaxDynamicSharedMemorySize, GE_SZ);
    cudaFuncSetAttribute(flash_kernel, cudaFuncAttributeMaxDynamicSharedMemorySize, FL_SZ);

    const int total4 = 3 * NX4 + 4 * NW4;
    cvt_kernel<<<total4 / 256, 256>>>(Q, K, V,
                                      (const float*)d_in[3], (const float*)d_in[5],
                                      (const float*)d_in[7], (const float*)d_in[9]);

    proj_kernel <<<dim3(DM / 128, MROWS / 128, 3), 256, GE_SZ>>>(bq, bk, bv);
    flash_kernel<<<dim3(S_ / 128, BH), 256, FL_SZ>>>();
    out_kernel  <<<dim3(DM / 128, MROWS / 128),   256, GE_SZ>>>(out, bo);
}

// round 17
// speedup vs baseline: 1.0239x; 1.0091x over previous
#include <cuda_runtime.h>
#include <cuda_bf16.h>
#include <cuda_fp16.h>
#include <cstdint>

// ===========================================================================
// MHA  B=2 S=2048 DM=1024 H=16 DK=64 — Round 16:
//   base = R12 (best known: 2-stage cp.async 128x128 fp16 GEMMs)
//   flash: 128-key macro-chunks (2x64 sub-tiles), double-buffered K/V sets,
//          ONE wait + ONE barrier per 128 keys (4x fewer sync events)
// ===========================================================================

#define B_    2
#define S_    2048
#define H_    16
#define DK    64
#define DM    1024
#define MROWS (B_ * S_)   // 4096
#define BH    (B_ * H_)   // 32

typedef unsigned short u16;

// ---------------- device scratch ----------------
__device__ u16 g_Q16[MROWS * DM], g_K16in[MROWS * DM], g_V16[MROWS * DM];
__device__ u16 g_Wq16[DM * DM], g_Wk16[DM * DM], g_Wv16[DM * DM], g_Wo16[DM * DM];
__device__ u16 g_q16[BH * S_ * DK];            // fp16, pre-scaled by 0.125
__device__ u16 g_k16[BH * S_ * DK];
__device__ u16 g_vT16[BH * DK * S_];           // transposed V
__device__ u16 g_ctx16[MROWS * DM];

// ---------------- helpers ----------------
__device__ __forceinline__ uint32_t smem_u32(const void* p) {
    uint32_t a;
    asm("{ .reg .u64 t; cvta.to.shared.u64 t, %1; cvt.u32.u64 %0, t; }" : "=r"(a) : "l"(p));
    return a;
}
#define SWZ(b) ((b) ^ (((b) >> 3) & 0x70))

__device__ __forceinline__ void ldsm4(uint32_t r[4], uint32_t addr) {
    asm volatile("ldmatrix.sync.aligned.m8n8.x4.shared.b16 {%0,%1,%2,%3}, [%4];"
        : "=r"(r[0]), "=r"(r[1]), "=r"(r[2]), "=r"(r[3]) : "r"(addr));
}
__device__ __forceinline__ void cpa16(uint32_t dst, const void* src) {
    asm volatile("cp.async.cg.shared.global [%0], [%1], 16;" :: "r"(dst), "l"(src) : "memory");
}
#define CP_COMMIT() asm volatile("cp.async.commit_group;" ::: "memory")
#define CP_WAIT0()  asm volatile("cp.async.wait_group 0;" ::: "memory")

__device__ __forceinline__ void hmma_f16(float c[4], const uint32_t a[4], const uint32_t b[2]) {
    asm volatile("mma.sync.aligned.m16n8k16.row.col.f32.f16.f16.f32 "
        "{%0,%1,%2,%3}, {%4,%5,%6,%7}, {%8,%9}, {%0,%1,%2,%3};"
        : "+f"(c[0]), "+f"(c[1]), "+f"(c[2]), "+f"(c[3])
        : "r"(a[0]), "r"(a[1]), "r"(a[2]), "r"(a[3]), "r"(b[0]), "r"(b[1]));
}
__device__ __forceinline__ uint32_t pkh2(float a, float b) {
    __half2 h2 = __floats2half2_rn(a, b);
    return *(uint32_t*)&h2;
}

// ---------------- proj/out pipelined smem: 2 stages x 32 KB ----------------
#define STG_A  0
#define STG_B  16384
#define STG_SZ 32768
#define GE_SZ  (2 * STG_SZ)   // 64 KB dynamic

// ---------------------------------------------------------------------------
// GEMM mainloop: block 128(M) x 128(N), warp tile 32x64, 2-stage cp.async.
// ---------------------------------------------------------------------------
__device__ __forceinline__ void mma_loop(
    const u16* __restrict__ Ap, int lda,
    const u16* __restrict__ Bp, int ldb,
    int K, char* sm, float acc[2][8][4])
{
    const int tid  = threadIdx.x;
    const int lane = tid & 31;
    const int wid  = tid >> 5;
    const int wm   = wid >> 1;
    const int wn   = wid & 1;
    const uint32_t smb = smem_u32(sm);

    const int rA  = wm * 32 + (lane & 15);
    const int cA  = (lane >> 4) << 4;
    const int rB0 = wn * 64 + (lane & 7) + ((lane & 16) >> 1);
    const int cB  = (lane & 8) << 1;

    auto issue = [&](int ch, uint32_t st) {
        const int k0 = ch << 6;
#pragma unroll
        for (int i = 0; i < 4; i++) {
            int e = (tid + (i << 8)) << 3;
            int row = e >> 6, col = e & 63;
            uint32_t sw = SWZ((uint32_t)(row * 128 + col * 2));
            cpa16(st + STG_A + sw, Ap + (size_t)row * lda + k0 + col);
            cpa16(st + STG_B + sw, Bp + (size_t)row * ldb + k0 + col);
        }
    };

    const int nch = K >> 6;
    issue(0, smb); CP_COMMIT();
    for (int ch = 0; ch < nch; ch++) {
        CP_WAIT0();
        __syncthreads();
        if (ch + 1 < nch) { issue(ch + 1, smb + ((ch + 1) & 1) * STG_SZ); CP_COMMIT(); }
        const uint32_t st = smb + (ch & 1) * STG_SZ;
#pragma unroll
        for (int ks = 0; ks < 4; ks++) {
            uint32_t a[2][4];
            ldsm4(a[0], st + STG_A + SWZ((uint32_t)((rA)      * 128 + cA + ks * 32)));
            ldsm4(a[1], st + STG_A + SWZ((uint32_t)((rA + 16) * 128 + cA + ks * 32)));
            uint32_t b[4][4];
#pragma unroll
            for (int nb = 0; nb < 4; nb++)
                ldsm4(b[nb], st + STG_B + SWZ((uint32_t)((rB0 + 16 * nb) * 128 + cB + ks * 32)));
#pragma unroll
            for (int i = 0; i < 2; i++)
#pragma unroll
                for (int j = 0; j < 8; j++) {
                    uint32_t bb[2] = { b[j >> 1][(j & 1) * 2], b[j >> 1][(j & 1) * 2 + 1] };
                    hmma_f16(acc[i][j], a[i], bb);
                }
        }
    }
}

// ---------------------------------------------------------------------------
// cvt (merged): all 7 fp32 tensors -> single fp16. One launch.
// ---------------------------------------------------------------------------
#define NX4 (MROWS * DM / 4)
#define NW4 (DM * DM / 4)
__global__ void cvt_kernel(const float* __restrict__ Q, const float* __restrict__ K,
                           const float* __restrict__ V, const float* __restrict__ Wq,
                           const float* __restrict__ Wk, const float* __restrict__ Wv,
                           const float* __restrict__ Wo)
{
    int i = blockIdx.x * blockDim.x + threadIdx.x;
    const float* src; u16* dst; int off;
    if (i < NX4)          { src = Q;  dst = g_Q16;   off = i; }
    else if (i < 2 * NX4) { src = K;  dst = g_K16in; off = i - NX4; }
    else if (i < 3 * NX4) { src = V;  dst = g_V16;   off = i - 2 * NX4; }
    else {
        int w = i - 3 * NX4;
        int t = w / NW4; off = w - t * NW4;
        if (t == 0)      { src = Wq; dst = g_Wq16; }
        else if (t == 1) { src = Wk; dst = g_Wk16; }
        else if (t == 2) { src = Wv; dst = g_Wv16; }
        else             { src = Wo; dst = g_Wo16; }
    }
    float4 v = ((const float4*)src)[off];
    ((uint2*)dst)[off] = make_uint2(pkh2(v.x, v.y), pkh2(v.z, v.w));
}

// ---------------------------------------------------------------------------
// proj: z=0 -> q (fp16, x0.125), z=1 -> k, z=2 -> vT. grid (8, 32, 3)
// ---------------------------------------------------------------------------
__global__ __launch_bounds__(256) void proj_kernel(
    const float* __restrict__ bq, const float* __restrict__ bk,
    const float* __restrict__ bv)
{
    extern __shared__ char sm[];
    const int z  = blockIdx.z;
    const int n0 = blockIdx.x * 128;
    const int m0 = blockIdx.y * 128;

    const u16 *Ap, *Bp;
    const float* bias;
    if (z == 0)      { Ap = g_Q16;   Bp = g_Wq16; bias = bq; }
    else if (z == 1) { Ap = g_K16in; Bp = g_Wk16; bias = bk; }
    else             { Ap = g_V16;   Bp = g_Wv16; bias = bv; }

    float acc[2][8][4];
#pragma unroll
    for (int i = 0; i < 2; i++)
#pragma unroll
        for (int j = 0; j < 8; j++)
#pragma unroll
            for (int q = 0; q < 4; q++) acc[i][j][q] = 0.f;

    mma_loop(Ap + (size_t)m0 * DM, DM, Bp + (size_t)n0 * DM, DM, DM, sm, acc);

    const int lane = threadIdx.x & 31, wid = threadIdx.x >> 5;
    const int wm = wid >> 1, wn = wid & 1;
#pragma unroll
    for (int i = 0; i < 2; i++)
#pragma unroll
    for (int half = 0; half < 2; half++) {
        const int r = m0 + wm * 32 + i * 16 + (lane >> 2) + half * 8;
        const int b = r >> 11, s = r & (S_ - 1);
#pragma unroll
        for (int j = 0; j < 8; j++) {
            const int n = n0 + wn * 64 + j * 8 + 2 * (lane & 3);
            float v0 = acc[i][j][half * 2]     + bias[n];
            float v1 = acc[i][j][half * 2 + 1] + bias[n + 1];
            const int hh = n >> 6, dk = n & 63;
            const size_t bh = (size_t)(b * H_ + hh);
            if (z == 0) {
                *(uint32_t*)&g_q16[(bh * S_ + s) * DK + dk] = pkh2(v0 * 0.125f, v1 * 0.125f);
            } else if (z == 1) {
                *(uint32_t*)&g_k16[(bh * S_ + s) * DK + dk] = pkh2(v0, v1);
            } else {
                __half h0 = __float2half_rn(v0), h1 = __float2half_rn(v1);
                g_vT16[(bh * DK + dk)     * S_ + s] = *(u16*)&h0;
                g_vT16[(bh * DK + dk + 1) * S_ + s] = *(u16*)&h1;
            }
        }
    }
}

// ---------------- flash smem layout (dynamic, 80 KB) ----------------
// Q 16 KB; 2 sets x { K: 2x8 KB sub-tiles, V: 2x8 KB sub-tiles } = 64 KB
#define FQ       0
#define FSET(s)  (16384 + (s) * 32768)
#define FK_OF(h) ((h) * 8192)             // K sub-tile h within set
#define FV_OF(h) (16384 + (h) * 8192)     // V sub-tile h within set
#define FL_SZ    (16384 + 2 * 32768)      // 81920

// ---------------------------------------------------------------------------
// flash: fused scores+softmax+pv, fp16 MMA, register-P.
// 128-key macro-chunks, double-buffered sets, 1 wait + 1 barrier per macro.
// warp = 16 rows x 64 keys (per half). grid (16, BH), 256 threads.
// ---------------------------------------------------------------------------
__global__ __launch_bounds__(256, 2) void flash_kernel()
{
    extern __shared__ char sm[];
    const uint32_t smb = smem_u32(sm);

    const int bh = blockIdx.y;
    const int m0 = blockIdx.x * 128;
    const size_t qoff = (size_t)bh * S_ * DK;
    const size_t voff = (size_t)bh * DK * S_;

    const int tid  = threadIdx.x;
    const int lane = tid & 31;
    const int wid  = tid >> 5;
    const int g    = lane >> 2;
    const int tq   = lane & 3;

    const int rA  = wid * 16 + (lane & 15);
    const int cA  = (lane >> 4) << 4;
    const int rB0 = (lane & 7) + ((lane & 16) >> 1);
    const int cB  = (lane & 8) << 1;

    // issue one 128-key macro-chunk (K + V, both halves) into set `set`
    auto issueKV = [&](int n0, int set) {
        const uint32_t base = smb + FSET(set);
#pragma unroll
        for (int h = 0; h < 2; h++) {
#pragma unroll
            for (int i = 0; i < 2; i++) {
                int e = (tid + (i << 8)) << 3;
                int row = e >> 6, col = e & 63;
                uint32_t sw = SWZ((uint32_t)(row * 128 + col * 2));
                cpa16(base + FK_OF(h) + sw,
                      g_k16 + qoff + (size_t)(n0 + h * 64 + row) * DK + col);
                cpa16(base + FV_OF(h) + sw,
                      g_vT16 + voff + (size_t)row * S_ + n0 + h * 64 + col);
            }
        }
    };

    // ---- prologue: Q + macro(0) in one group ----
#pragma unroll
    for (int i = 0; i < 4; i++) {
        int e = (tid + (i << 8)) << 3;
        int row = e >> 6, col = e & 63;
        uint32_t sw = SWZ((uint32_t)(row * 128 + col * 2));
        cpa16(smb + FQ + sw, g_q16 + qoff + (size_t)(m0 + row) * DK + col);
    }
    issueKV(0, 0);
    CP_COMMIT();

    float acc_o[8][4];
#pragma unroll
    for (int j = 0; j < 8; j++)
#pragma unroll
        for (int q = 0; q < 4; q++) acc_o[j][q] = 0.f;
    float m0r = -1e30f, m1r = -1e30f, s0r = 0.f, s1r = 0.f;

    const int NMC = S_ / 128;   // 16 macro-chunks
    for (int mc = 0; mc < NMC; mc++) {
        CP_WAIT0();
        __syncthreads();   // macro(mc) resident; all warps done with other set
        if (mc + 1 < NMC) { issueKV((mc + 1) << 7, (mc + 1) & 1); CP_COMMIT(); }

        const uint32_t setb = smb + FSET(mc & 1);

#pragma unroll
        for (int h = 0; h < 2; h++) {
            const uint32_t kbuf = setb + FK_OF(h);
            const uint32_t vbuf = setb + FV_OF(h);

            // ---- S = q k^T, single-pass fp16 (q pre-scaled) ----
            float s[8][4];
#pragma unroll
            for (int j = 0; j < 8; j++)
#pragma unroll
                for (int q = 0; q < 4; q++) s[j][q] = 0.f;
#pragma unroll
            for (int ks = 0; ks < 4; ks++) {
                uint32_t a[4];
                ldsm4(a, smb + FQ + SWZ((uint32_t)(rA * 128 + cA + ks * 32)));
                uint32_t b[4][4];
#pragma unroll
                for (int nb = 0; nb < 4; nb++)
                    ldsm4(b[nb], kbuf + SWZ((uint32_t)((rB0 + 16 * nb) * 128 + cB + ks * 32)));
#pragma unroll
                for (int j = 0; j < 8; j++) {
                    uint32_t bb[2] = { b[j >> 1][(j & 1) * 2], b[j >> 1][(j & 1) * 2 + 1] };
                    hmma_f16(s[j], a, bb);
                }
            }

            // ---- online softmax, fully in registers (rows g and g+8) ----
            float mx0 = -1e30f, mx1 = -1e30f;
#pragma unroll
            for (int j = 0; j < 8; j++) {
                mx0 = fmaxf(mx0, fmaxf(s[j][0], s[j][1]));
                mx1 = fmaxf(mx1, fmaxf(s[j][2], s[j][3]));
            }
            mx0 = fmaxf(mx0, __shfl_xor_sync(~0u, mx0, 1));
            mx0 = fmaxf(mx0, __shfl_xor_sync(~0u, mx0, 2));
            mx1 = fmaxf(mx1, __shfl_xor_sync(~0u, mx1, 1));
            mx1 = fmaxf(mx1, __shfl_xor_sync(~0u, mx1, 2));

            const float mn0 = fmaxf(m0r, mx0), mn1 = fmaxf(m1r, mx1);
            const float al0 = __expf(m0r - mn0), al1 = __expf(m1r - mn1);
            m0r = mn0; m1r = mn1;

            float ps0 = 0.f, ps1 = 0.f;
#pragma unroll
            for (int j = 0; j < 8; j++) {
                s[j][0] = __expf(s[j][0] - mn0);
                s[j][1] = __expf(s[j][1] - mn0);
                s[j][2] = __expf(s[j][2] - mn1);
                s[j][3] = __expf(s[j][3] - mn1);
                ps0 += s[j][0] + s[j][1];
                ps1 += s[j][2] + s[j][3];
                acc_o[j][0] *= al0; acc_o[j][1] *= al0;
                acc_o[j][2] *= al1; acc_o[j][3] *= al1;
            }
            ps0 += __shfl_xor_sync(~0u, ps0, 1);
            ps0 += __shfl_xor_sync(~0u, ps0, 2);
            ps1 += __shfl_xor_sync(~0u, ps1, 1);
            ps1 += __shfl_xor_sync(~0u, ps1, 2);
            s0r = s0r * al0 + ps0;
            s1r = s1r * al1 + ps1;

            // ---- O += P @ V, single-pass fp16, P packed from registers ----
#pragma unroll
            for (int ks = 0; ks < 4; ks++) {
                uint32_t a[4];
                a[0] = pkh2(s[2 * ks][0],     s[2 * ks][1]);
                a[1] = pkh2(s[2 * ks][2],     s[2 * ks][3]);
                a[2] = pkh2(s[2 * ks + 1][0], s[2 * ks + 1][1]);
                a[3] = pkh2(s[2 * ks + 1][2], s[2 * ks + 1][3]);
                uint32_t v[4][4];
#pragma unroll
                for (int nb = 0; nb < 4; nb++)
                    ldsm4(v[nb], vbuf + SWZ((uint32_t)((rB0 + 16 * nb) * 128 + cB + ks * 32)));
#pragma unroll
                for (int j = 0; j < 8; j++) {
                    uint32_t bb[2] = { v[j >> 1][(j & 1) * 2], v[j >> 1][(j & 1) * 2 + 1] };
                    hmma_f16(acc_o[j], a, bb);
                }
            }
        }
    }

    // ---- epilogue: normalize, write ctx (single fp16) ----
    const int b = bh >> 4, h = bh & 15;
    const float inv0 = 1.0f / s0r, inv1 = 1.0f / s1r;
    const int r0 = m0 + wid * 16 + g;
    const size_t ro0 = ((size_t)(b * S_ + r0)) * DM + h * DK;
    const size_t ro1 = ro0 + (size_t)8 * DM;
#pragma unroll
    for (int j = 0; j < 8; j++) {
        const int d = 8 * j + 2 * tq;
        *(uint32_t*)&g_ctx16[ro0 + d] = pkh2(acc_o[j][0] * inv0, acc_o[j][1] * inv0);
        *(uint32_t*)&g_ctx16[ro1 + d] = pkh2(acc_o[j][2] * inv1, acc_o[j][3] * inv1);
    }
}

// ---------------------------------------------------------------------------
// out: out = ctx @ Wo^T + bo.  grid (8, 32)
// ---------------------------------------------------------------------------
__global__ __launch_bounds__(256) void out_kernel(float* __restrict__ out,
                                                  const float* __restrict__ bo)
{
    extern __shared__ char sm[];
    const int n0 = blockIdx.x * 128;
    const int m0 = blockIdx.y * 128;

    float acc[2][8][4];
#pragma unroll
    for (int i = 0; i < 2; i++)
#pragma unroll
        for (int j = 0; j < 8; j++)
#pragma unroll
            for (int q = 0; q < 4; q++) acc[i][j][q] = 0.f;

    mma_loop(g_ctx16 + (size_t)m0 * DM, DM, g_Wo16 + (size_t)n0 * DM, DM, DM, sm, acc);

    const int lane = threadIdx.x & 31, wid = threadIdx.x >> 5;
    const int wm = wid >> 1, wn = wid & 1;
#pragma unroll
    for (int i = 0; i < 2; i++)
#pragma unroll
    for (int half = 0; half < 2; half++) {
        const int r = m0 + wm * 32 + i * 16 + (lane >> 2) + half * 8;
#pragma unroll
        for (int j = 0; j < 8; j++) {
            const int c = n0 + wn * 64 + j * 8 + 2 * (lane & 3);
            float2 o = { acc[i][j][half * 2] + bo[c],
                         acc[i][j][half * 2 + 1] + bo[c + 1] };
            *(float2*)(out + (size_t)r * DM + c) = o;
        }
    }
}

// ---------------------------------------------------------------------------
// launcher — no __device__ symbol referenced from host code.
// ---------------------------------------------------------------------------
extern "C" void kernel_launch(void* const* d_in, const int* in_sizes, int n_in,
                              void* d_out, int out_size)
{
    (void)in_sizes; (void)n_in; (void)out_size;
    const float* Q  = (const float*)d_in[0];
    const float* K  = (const float*)d_in[1];
    const float* V  = (const float*)d_in[2];
    const float* bq = (const float*)d_in[4];
    const float* bk = (const float*)d_in[6];
    const float* bv = (const float*)d_in[8];
    const float* bo = (const float*)d_in[10];
    float* out = (float*)d_out;

    cudaFuncSetAttribute(proj_kernel,  cudaFuncAttributeMaxDynamicSharedMemorySize, GE_SZ);
    cudaFuncSetAttribute(out_kernel,   cudaFuncAttributeMaxDynamicSharedMemorySize, GE_SZ);
    cudaFuncSetAttribute(flash_kernel, cudaFuncAttributeMaxDynamicSharedMemorySize, FL_SZ);

    const int total4 = 3 * NX4 + 4 * NW4;
    cvt_kernel<<<total4 / 256, 256>>>(Q, K, V,
                                      (const float*)d_in[3], (const float*)d_in[5],
                                      (const float*)d_in[7], (const float*)d_in[9]);

    proj_kernel <<<dim3(DM / 128, MROWS / 128, 3), 256, GE_SZ>>>(bq, bk, bv);
    flash_kernel<<<dim3(S_ / 128, BH), 256, FL_SZ>>>();
    out_kernel  <<<dim3(DM / 128, MROWS / 128),   256, GE_SZ>>>(out, bo);
}